// round 1
// baseline (speedup 1.0000x reference)
#include <cuda_runtime.h>

#define BATCH 8
#define KLEN  8192
#define HDIM  512
#define ROWS  (BATCH * KLEN)
#define EPSV  1e-8f

// Scratch (allocation-free rule: __device__ globals)
__device__ float g_sum[ROWS];
__device__ float g_sq[ROWS];
__device__ float g_mean[ROWS];
__device__ float g_inv[ROWS];

// ---------------- Pass 1: per-(b,k) row sum / sqsum, one warp per row ----------------
__global__ __launch_bounds__(256) void row_reduce_kernel(const float* __restrict__ x) {
    int gwarp = (blockIdx.x * 256 + threadIdx.x) >> 5;   // global warp id == row id
    int lane  = threadIdx.x & 31;
    if (gwarp >= ROWS) return;

    const float4* p = reinterpret_cast<const float4*>(x) + (size_t)gwarp * (HDIM / 4);
    float s = 0.f, q = 0.f;
#pragma unroll
    for (int j = 0; j < 4; j++) {
        float4 v = p[lane + 32 * j];
        s += (v.x + v.y) + (v.z + v.w);
        q += (v.x * v.x + v.y * v.y) + (v.z * v.z + v.w * v.w);
    }
#pragma unroll
    for (int o = 16; o; o >>= 1) {
        s += __shfl_xor_sync(0xffffffffu, s, o);
        q += __shfl_xor_sync(0xffffffffu, q, o);
    }
    if (lane == 0) {
        g_sum[gwarp] = s;
        g_sq[gwarp]  = q;
    }
}

// ---------------- Pass 2: per-batch inclusive scan over K, compute mean/inv_std ----------------
__global__ __launch_bounds__(1024) void scan_kernel() {
    __shared__ float ssum[32];
    __shared__ float ssq[32];

    const int b    = blockIdx.x;       // batch
    const int t    = threadIdx.x;      // 0..1023
    const int lane = t & 31;
    const int warp = t >> 5;
    const int base = b * KLEN + t * 8; // 8 steps per thread

    float ls[8], lq[8];
    float rs = 0.f, rq = 0.f;
#pragma unroll
    for (int i = 0; i < 8; i++) {
        rs += g_sum[base + i]; ls[i] = rs;
        rq += g_sq[base + i];  lq[i] = rq;
    }

    // warp-level inclusive scan of per-thread totals
    float ws = rs, wq = rq;
#pragma unroll
    for (int o = 1; o < 32; o <<= 1) {
        float a = __shfl_up_sync(0xffffffffu, ws, o);
        float c = __shfl_up_sync(0xffffffffu, wq, o);
        if (lane >= o) { ws += a; wq += c; }
    }
    if (lane == 31) { ssum[warp] = ws; ssq[warp] = wq; }
    __syncthreads();

    if (warp == 0) {
        float vs = ssum[lane], vq = ssq[lane];
#pragma unroll
        for (int o = 1; o < 32; o <<= 1) {
            float a = __shfl_up_sync(0xffffffffu, vs, o);
            float c = __shfl_up_sync(0xffffffffu, vq, o);
            if (lane >= o) { vs += a; vq += c; }
        }
        ssum[lane] = vs; ssq[lane] = vq;
    }
    __syncthreads();

    float ex_s = (warp ? ssum[warp - 1] : 0.f) + (ws - rs);  // exclusive prefix for this thread
    float ex_q = (warp ? ssq[warp - 1]  : 0.f) + (wq - rq);

#pragma unroll
    for (int i = 0; i < 8; i++) {
        float cs   = ex_s + ls[i];
        float cq   = ex_q + lq[i];
        float cnt  = (float)((t * 8 + i + 1) * HDIM);
        float mean = cs / cnt;
        float var  = cq / cnt - mean * mean;
        g_mean[base + i] = mean;
        g_inv[base + i]  = rsqrtf(var + EPSV);
    }
}

// ---------------- Pass 3: elementwise normalize ----------------
__global__ __launch_bounds__(256) void norm_kernel(const float* __restrict__ x,
                                                   const float* __restrict__ gamma,
                                                   const float* __restrict__ beta,
                                                   float* __restrict__ out) {
    // one float4 per thread; 128 float4 per row
    long i = (long)blockIdx.x * 256 + threadIdx.x;
    int row = (int)(i >> 7);
    int h4  = (int)(i & 127);

    float mean = g_mean[row];
    float inv  = g_inv[row];

    float4 v  = reinterpret_cast<const float4*>(x)[i];
    float4 g  = reinterpret_cast<const float4*>(gamma)[h4];
    float4 bb = reinterpret_cast<const float4*>(beta)[h4];

    float4 o;
    o.x = g.x * (v.x - mean) * inv + bb.x;
    o.y = g.y * (v.y - mean) * inv + bb.y;
    o.z = g.z * (v.z - mean) * inv + bb.z;
    o.w = g.w * (v.w - mean) * inv + bb.w;
    reinterpret_cast<float4*>(out)[i] = o;
}

extern "C" void kernel_launch(void* const* d_in, const int* in_sizes, int n_in,
                              void* d_out, int out_size) {
    const float* x     = (const float*)d_in[0];
    const float* gamma = (const float*)d_in[1];
    const float* beta  = (const float*)d_in[2];
    float* out         = (float*)d_out;

    // Pass 1: 8 warps (rows) per 256-thread block
    row_reduce_kernel<<<ROWS / 8, 256>>>(x);

    // Pass 2: one block per batch
    scan_kernel<<<BATCH, 1024>>>();

    // Pass 3: 8M float4s, 256 threads/block
    long n4 = (long)ROWS * (HDIM / 4);
    norm_kernel<<<(unsigned)(n4 / 256), 256>>>(x, gamma, beta, out);
}